// round 8
// baseline (speedup 1.0000x reference)
#include <cuda_runtime.h>
#include <cuda_bf16.h>

#define ROWS 4096
#define COLS 8192
#define TPB  256
#define VEC_ITERS (COLS / 4 / TPB)   // 8 float4 loads per thread

__global__ __launch_bounds__(TPB, 6)
void consecutive_loss_kernel(const float* __restrict__ x, float* __restrict__ out) {
    __shared__ float s[COLS];                 // 32 KiB row stage
    __shared__ int   s_cnt[TPB / 32];
    __shared__ float s_sum[TPB / 32];

    const int row = blockIdx.x;
    if (row == 0) return;                     // reference skips row 0 entirely

    const int tid = threadIdx.x;
    const float4* __restrict__ xr =
        reinterpret_cast<const float4*>(x + (size_t)row * COLS);
    float4* sv = reinterpret_cast<float4*>(s);

    // Pass 1: stream row from HBM (coalesced float4, MLP=8 front-batched),
    // count nonzeros, stage into shared.
    int cnt = 0;
    #pragma unroll
    for (int i = 0; i < VEC_ITERS; i++) {
        float4 v = xr[tid + i * TPB];
        cnt += (v.x != 0.0f) + (v.y != 0.0f) + (v.z != 0.0f) + (v.w != 0.0f);
        sv[tid + i * TPB] = v;
    }

    // Block-reduce nonzero count -> L (real_length)
    #pragma unroll
    for (int o = 16; o > 0; o >>= 1) cnt += __shfl_xor_sync(0xFFFFFFFFu, cnt, o);
    if ((tid & 31) == 0) s_cnt[tid >> 5] = cnt;
    __syncthreads();                          // also publishes s[] for pass 2

    int L = 0;
    #pragma unroll
    for (int w = 0; w < TPB / 32; w++) L += s_cnt[w];

    // Pass 2: sum of |x[pos] - x[pos-1]| for pos in [1, min(L,COLS)-1], from smem.
    const int bound = (L < COLS) ? L : COLS;
    float sum = 0.0f;
    for (int pos = tid + 1; pos < bound; pos += TPB) {
        sum += fabsf(s[pos] - s[pos - 1]);
    }

    #pragma unroll
    for (int o = 16; o > 0; o >>= 1) sum += __shfl_xor_sync(0xFFFFFFFFu, sum, o);
    if ((tid & 31) == 0) s_sum[tid >> 5] = sum;
    __syncthreads();

    if (tid == 0) {
        float total = 0.0f;
        #pragma unroll
        for (int w = 0; w < TPB / 32; w++) total += s_sum[w];
        if (L > 0) {
            atomicAdd(out, total / (float)L * (1.0f / (float)ROWS));
        }
    }
}

extern "C" void kernel_launch(void* const* d_in, const int* in_sizes, int n_in,
                              void* d_out, int out_size) {
    const float* x = (const float*)d_in[0];
    float* out = (float*)d_out;
    // d_out is poisoned to 0xAA before timing; zero it (memset node is
    // graph-capturable).
    cudaMemsetAsync(out, 0, sizeof(float));
    consecutive_loss_kernel<<<ROWS, TPB>>>(x, out);
}

// round 10
// speedup vs baseline: 1.1425x; 1.1425x over previous
#include <cuda_runtime.h>
#include <cuda_bf16.h>

#define ROWS   4096
#define COLS   8192
#define TPB    256
#define CHUNKS (COLS / 4 / TPB)   // 8 float4 chunks per thread

__global__ __launch_bounds__(TPB, 5)
void consecutive_loss_kernel(const float* __restrict__ x, float* __restrict__ out) {
    __shared__ int   s_cnt[TPB / 32];
    __shared__ float s_sum[TPB / 32];

    const int row = blockIdx.x;
    if (row == 0) return;                       // reference skips row 0

    const int tid = threadIdx.x;
    const float* __restrict__ xrow = x + (size_t)row * COLS;
    const float4* __restrict__ xr = reinterpret_cast<const float4*>(xrow);

    // Front-batched loads: 8 independent float4 LDGs (MLP=8).
    float4 v[CHUNKS];
    #pragma unroll
    for (int i = 0; i < CHUNKS; i++) v[i] = xr[tid + i * TPB];

    // Per-chunk: nonzero count + position-contiguous |diff| partial sum.
    // Chunk i covers elements [4j, 4j+3], j = tid + i*TPB; its diff positions
    // are 4j (boundary, prev = element 4j-1) .. 4j+3.
    int   cnt = 0;
    float csum[CHUNKS];
    #pragma unroll
    for (int i = 0; i < CHUNKS; i++) {
        float4 a = v[i];
        cnt += (a.x != 0.0f) + (a.y != 0.0f) + (a.z != 0.0f) + (a.w != 0.0f);

        const int j = tid + i * TPB;
        float prev = __shfl_up_sync(0xFFFFFFFFu, a.w, 1);  // lane-1's elem 4j-1
        if ((tid & 31) == 0)                               // cross-warp boundary
            prev = (j > 0) ? xrow[4 * j - 1] : 0.0f;       // L1/L2 hit

        float s = fabsf(a.y - a.x) + fabsf(a.z - a.y) + fabsf(a.w - a.z);
        if (j > 0) s += fabsf(a.x - prev);                 // pos 4j (needs pos>=1)
        csum[i] = s;
    }

    // Block-reduce nonzero count -> L.
    #pragma unroll
    for (int o = 16; o > 0; o >>= 1) cnt += __shfl_xor_sync(0xFFFFFFFFu, cnt, o);
    if ((tid & 31) == 0) s_cnt[tid >> 5] = cnt;
    __syncthreads();

    int L = 0;
    #pragma unroll
    for (int w = 0; w < TPB / 32; w++) L += s_cnt[w];

    // Prefix mask (pos < L) applied chunk-wise: full / none / one straddler.
    float sum = 0.0f;
    #pragma unroll
    for (int i = 0; i < CHUNKS; i++) {
        const int base = 4 * (tid + i * TPB);              // first diff pos
        if (base + 3 < L) {
            sum += csum[i];
        } else if (base < L) {                             // straddling chunk (rare)
            float p = (base > 0) ? xrow[base - 1] : 0.0f;  // L2 hit
            #pragma unroll
            for (int d = 0; d < 4; d++) {
                const int pos = base + d;
                const float c = xrow[pos];
                if (pos >= 1 && pos < L) sum += fabsf(c - p);
                p = c;
            }
        }
    }

    // Block-reduce the masked diff sum.
    #pragma unroll
    for (int o = 16; o > 0; o >>= 1) sum += __shfl_xor_sync(0xFFFFFFFFu, sum, o);
    if ((tid & 31) == 0) s_sum[tid >> 5] = sum;
    __syncthreads();

    if (tid == 0) {
        float total = 0.0f;
        #pragma unroll
        for (int w = 0; w < TPB / 32; w++) total += s_sum[w];
        if (L > 0) {
            atomicAdd(out, total / (float)L * (1.0f / (float)ROWS));
        }
    }
}

extern "C" void kernel_launch(void* const* d_in, const int* in_sizes, int n_in,
                              void* d_out, int out_size) {
    const float* x = (const float*)d_in[0];
    float* out = (float*)d_out;
    // d_out is poisoned to 0xAA before timing; zero it (capturable memset node).
    cudaMemsetAsync(out, 0, sizeof(float));
    consecutive_loss_kernel<<<ROWS, TPB>>>(x, out);
}

// round 12
// speedup vs baseline: 1.1515x; 1.0079x over previous
#include <cuda_runtime.h>
#include <cuda_bf16.h>

#define ROWS   4096
#define COLS   8192
#define TPB    256
#define GRID   1184               // 148 SMs x 8 CTAs
#define NCHUNK (COLS / 4 / TPB)   // 8 chunks/thread, processed in 2 batches of 4

__global__ __launch_bounds__(TPB, 8)
void consecutive_loss_kernel(const float* __restrict__ x, float* __restrict__ out) {
    __shared__ int   s_cnt[TPB / 32];
    __shared__ float s_sum[TPB / 32];

    const int tid  = threadIdx.x;
    float cta_acc  = 0.0f;        // meaningful on tid 0 only

    for (int row = blockIdx.x; row < ROWS; row += GRID) {
        if (row == 0) continue;   // reference skips row 0

        const float* __restrict__ xrow = x + (size_t)row * COLS;
        const float4* __restrict__ xr  = reinterpret_cast<const float4*>(xrow);

        int   cnt = 0;
        float spec = 0.0f;        // speculative sum: all diffs pos in [1, COLS-1]

        #pragma unroll
        for (int b = 0; b < 2; b++) {
            // Batch of 4 independent float4 loads (MLP=4; 64 warps/SM cover latency).
            float4 v[4];
            #pragma unroll
            for (int i = 0; i < 4; i++) v[i] = xr[tid + (b * 4 + i) * TPB];

            #pragma unroll
            for (int i = 0; i < 4; i++) {
                float4 a = v[i];
                cnt += (a.x != 0.0f) + (a.y != 0.0f) + (a.z != 0.0f) + (a.w != 0.0f);

                const int j = tid + (b * 4 + i) * TPB;      // chunk index
                float prev = __shfl_up_sync(0xFFFFFFFFu, a.w, 1);
                if ((tid & 31) == 0)                        // cross-warp boundary
                    prev = (j > 0) ? xrow[4 * j - 1] : 0.0f; // L1 hit

                float s = fabsf(a.y - a.x) + fabsf(a.z - a.y) + fabsf(a.w - a.z);
                if (j > 0) s += fabsf(a.x - prev);          // pos 4j (pos>=1 only)
                spec += s;
            }
        }

        // Block-reduce nonzero count -> L.
        #pragma unroll
        for (int o = 16; o > 0; o >>= 1) cnt += __shfl_xor_sync(0xFFFFFFFFu, cnt, o);
        if ((tid & 31) == 0) s_cnt[tid >> 5] = cnt;
        __syncthreads();

        int L = 0;
        #pragma unroll
        for (int w = 0; w < TPB / 32; w++) L += s_cnt[w];

        // Correction: subtract diffs with pos >= L (prefix mask). Never taken
        // when L == COLS (dense rows); reloads hit L1/L2.
        if (L < COLS) {
            #pragma unroll
            for (int c = 0; c < NCHUNK; c++) {
                const int base = 4 * (tid + c * TPB);
                int lo = base > L ? base : L;
                if (lo < 1) lo = 1;
                for (int pos = lo; pos <= base + 3; pos++)
                    spec -= fabsf(xrow[pos] - xrow[pos - 1]);
            }
        }

        // Block-reduce the (corrected) diff sum.
        #pragma unroll
        for (int o = 16; o > 0; o >>= 1) spec += __shfl_xor_sync(0xFFFFFFFFu, spec, o);
        if ((tid & 31) == 0) s_sum[tid >> 5] = spec;
        __syncthreads();

        if (tid == 0) {
            float total = 0.0f;
            #pragma unroll
            for (int w = 0; w < TPB / 32; w++) total += s_sum[w];
            if (L > 0) cta_acc += total / (float)L;
        }
        // Smem reuse across rows is safe: each array's writes in iteration
        // n+1 are separated from its reads in iteration n by a barrier.
    }

    if (tid == 0 && cta_acc != 0.0f) {
        atomicAdd(out, cta_acc * (1.0f / (float)ROWS));
    }
}

extern "C" void kernel_launch(void* const* d_in, const int* in_sizes, int n_in,
                              void* d_out, int out_size) {
    const float* x = (const float*)d_in[0];
    float* out = (float*)d_out;
    // d_out is poisoned to 0xAA before timing; zero it (capturable memset node).
    cudaMemsetAsync(out, 0, sizeof(float));
    consecutive_loss_kernel<<<GRID, TPB>>>(x, out);
}